// round 14
// baseline (speedup 1.0000x reference)
#include <cuda_runtime.h>
#include <cstdint>

#define NN 50000
#define EE 800000
#define IC 128
#define OC 64

typedef unsigned long long u64;

// ---------------- device scratch (static, allocation-free) ----------------
__device__ float g_dinv[NN];
__device__ int   g_degcnt[NN];
__device__ int   g_rowptr[NN + 1];
__device__ int   g_cursor[NN];
__device__ int2  g_cw[EE];               // packed (src, weight-bits)
__device__ float g_h[(size_t)NN * 128];
__device__ float g_a[(size_t)NN * 128];
__device__ float g_z[(size_t)NN * 64];

// ---------------- f32x2 helpers ----------------
__device__ __forceinline__ u64 pack2(float v) {
    u64 r;
    asm("mov.b64 %0, {%1, %2};" : "=l"(r) : "r"(__float_as_uint(v)), "r"(__float_as_uint(v)));
    return r;
}
__device__ __forceinline__ void unpack2(u64 v, float& lo, float& hi) {
    unsigned a, b;
    asm("mov.b64 {%0, %1}, %2;" : "=r"(a), "=r"(b) : "l"(v));
    lo = __uint_as_float(a); hi = __uint_as_float(b);
}
__device__ __forceinline__ void ffma2(u64& d, u64 a, u64 b) {
    asm("fma.rn.f32x2 %0, %1, %2, %0;" : "+l"(d) : "l"(a), "l"(b));
}

// ---------------- CSR build ----------------
__global__ void k_zero_deg(int n) {
    int i = blockIdx.x * blockDim.x + threadIdx.x;
    if (i < n) g_degcnt[i] = 0;
}

// 4 edges per thread, int4 load -> MLP 4 on the atomic path
__global__ void k_deg_count(const int* __restrict__ dst, int e) {
    int i0 = (blockIdx.x * blockDim.x + threadIdx.x) * 4;
    if (i0 + 3 < e) {
        int4 d4 = *(const int4*)(dst + i0);
        atomicAdd(&g_degcnt[d4.x], 1);
        atomicAdd(&g_degcnt[d4.y], 1);
        atomicAdd(&g_degcnt[d4.z], 1);
        atomicAdd(&g_degcnt[d4.w], 1);
    } else {
        for (int i = i0; i < e; i++) atomicAdd(&g_degcnt[dst[i]], 1);
    }
}

// single-block exclusive scan -> rowptr/cursor + dinv
__global__ __launch_bounds__(1024) void k_scan(int n, int e) {
    __shared__ int warp_sums[32];
    __shared__ int warp_off[32];
    const int tid = threadIdx.x;
    const int lane = tid & 31;
    const int wid = tid >> 5;
    const int chunk = (n + 1023) / 1024;
    const int base = tid * chunk;
    const int lim = min(base + chunk, n);

    int s = 0;
    for (int i = base; i < lim; i++) s += g_degcnt[i];

    int v = s;
    #pragma unroll
    for (int o = 1; o < 32; o <<= 1) {
        int t = __shfl_up_sync(0xffffffffu, v, o);
        if (lane >= o) v += t;
    }
    if (lane == 31) warp_sums[wid] = v;
    __syncthreads();
    if (wid == 0) {
        int w = (lane < 32) ? warp_sums[lane] : 0;
        #pragma unroll
        for (int o = 1; o < 32; o <<= 1) {
            int t = __shfl_up_sync(0xffffffffu, w, o);
            if (lane >= o) w += t;
        }
        warp_off[lane] = w;
    }
    __syncthreads();

    int run = v - s + (wid ? warp_off[wid - 1] : 0);
    for (int i = base; i < lim; i++) {
        g_rowptr[i] = run;
        g_cursor[i] = run;
        run += g_degcnt[i];
        g_dinv[i] = rsqrtf((float)g_degcnt[i] + 1.0f);
    }
    if (tid == 0) g_rowptr[n] = e;
}

// 4 edges/thread, packed int2 store
__global__ void k_scatter(const int* __restrict__ src, const int* __restrict__ dst, int e) {
    int i0 = (blockIdx.x * blockDim.x + threadIdx.x) * 4;
    if (i0 + 3 < e) {
        int4 s4 = *(const int4*)(src + i0);
        int4 d4 = *(const int4*)(dst + i0);
        float ws0 = g_dinv[s4.x], ws1 = g_dinv[s4.y], ws2 = g_dinv[s4.z], ws3 = g_dinv[s4.w];
        float wd0 = g_dinv[d4.x], wd1 = g_dinv[d4.y], wd2 = g_dinv[d4.z], wd3 = g_dinv[d4.w];
        int p0 = atomicAdd(&g_cursor[d4.x], 1);
        int p1 = atomicAdd(&g_cursor[d4.y], 1);
        int p2 = atomicAdd(&g_cursor[d4.z], 1);
        int p3 = atomicAdd(&g_cursor[d4.w], 1);
        g_cw[p0] = make_int2(s4.x, __float_as_int(ws0 * wd0));
        g_cw[p1] = make_int2(s4.y, __float_as_int(ws1 * wd1));
        g_cw[p2] = make_int2(s4.z, __float_as_int(ws2 * wd2));
        g_cw[p3] = make_int2(s4.w, __float_as_int(ws3 * wd3));
    } else {
        for (int i = i0; i < e; i++) {
            int s = src[i], d = dst[i];
            int pos = atomicAdd(&g_cursor[d], 1);
            g_cw[pos] = make_int2(s, __float_as_int(g_dinv[s] * g_dinv[d]));
        }
    }
}

// ---------------- register-tiled GEMM with f32x2 ----------
// out = act(x) @ W (+ bias if BIAS)
template <int CIN, int COUT, bool RELU_IN, bool BIAS>
__global__ __launch_bounds__(256, 1) void k_gemm(
    const float* __restrict__ x, const float* __restrict__ W,
    const float* __restrict__ bias, float* __restrict__ out_h, int n) {
    constexpr int BM = 128;
    constexpr int TM = 8;
    constexpr int TN = COUT / 16;
    constexpr int CINP = CIN + 4;

    extern __shared__ float sm[];
    float* Ws = sm;
    float* As = sm + CIN * COUT;

    const int tid = threadIdx.x;
    const int tx = tid & 15;
    const int ty = tid >> 4;
    const int row0 = blockIdx.x * BM;

    {
        const float4* Wg = (const float4*)W;
        float4* Wsv = (float4*)Ws;
        #pragma unroll 4
        for (int i = tid; i < CIN * COUT / 4; i += 256) Wsv[i] = Wg[i];
    }
    {
        constexpr int K4 = CIN / 4;
        #pragma unroll 4
        for (int i = tid; i < BM * K4; i += 256) {
            int r = i / K4, k4 = i % K4;
            float4 v = make_float4(0.f, 0.f, 0.f, 0.f);
            int rg = row0 + r;
            if (rg < n) {
                v = ((const float4*)(x + (size_t)rg * CIN))[k4];
                if (RELU_IN) {
                    v.x = fmaxf(v.x, 0.f); v.y = fmaxf(v.y, 0.f);
                    v.z = fmaxf(v.z, 0.f); v.w = fmaxf(v.w, 0.f);
                }
            }
            float* d = &As[r * CINP + k4 * 4];
            d[0] = v.x; d[1] = v.y; d[2] = v.z; d[3] = v.w;
        }
    }
    __syncthreads();

    u64 acc[TM][TN / 2];
    #pragma unroll
    for (int i = 0; i < TM; i++)
        #pragma unroll
        for (int j = 0; j < TN / 2; j++) acc[i][j] = 0ull;

    const float* Bp = Ws + tx * TN;
    #pragma unroll 8
    for (int k = 0; k < CIN; k++) {
        u64 a2[TM];
        #pragma unroll
        for (int i = 0; i < TM; i++) a2[i] = pack2(As[(ty + 16 * i) * CINP + k]);
        #pragma unroll
        for (int j4 = 0; j4 < TN / 4; j4++) {
            ulonglong2 bb = *(const ulonglong2*)(Bp + k * COUT + j4 * 4);
            #pragma unroll
            for (int i = 0; i < TM; i++) {
                ffma2(acc[i][j4 * 2 + 0], a2[i], bb.x);
                ffma2(acc[i][j4 * 2 + 1], a2[i], bb.y);
            }
        }
    }

    #pragma unroll
    for (int i = 0; i < TM; i++) {
        int rg = row0 + ty + 16 * i;
        if (rg >= n) continue;
        #pragma unroll
        for (int j = 0; j < TN / 2; j++) {
            float c0, c1;
            unpack2(acc[i][j], c0, c1);
            int col = tx * TN + j * 2;
            if (BIAS) {
                float2 bv = *(const float2*)(bias + col);
                c0 += bv.x; c1 += bv.y;
            }
            *(float2*)(out_h + (size_t)rg * COUT + col) = make_float2(c0, c1);
        }
    }
}

// ---------------- mu|lv GEMM fused with reparameterize ----------
// writes out_mu, out_lv (into d_out) and z = mu + eps*exp(0.5*lv)
__global__ __launch_bounds__(256, 1) void k_gemm_mulv_z(
    const float* __restrict__ x,
    const float* __restrict__ Wmu, const float* __restrict__ Wlv,
    const float* __restrict__ bmu, const float* __restrict__ blv,
    const float* __restrict__ eps,
    float* __restrict__ out_mu, float* __restrict__ out_lv,
    float* __restrict__ z, int n) {
    constexpr int CIN = 64, COUT = 128, BM = 128, TM = 8, TN = 8, CINP = CIN + 4;
    constexpr int ZS = 132;  // smem stride for staged mu|lv tile

    extern __shared__ float sm[];
    float* Ws = sm;                 // [64][128]: cols 0-63 mu, 64-127 lv
    float* As = sm + CIN * COUT;

    const int tid = threadIdx.x;
    const int tx = tid & 15;
    const int ty = tid >> 4;
    const int row0 = blockIdx.x * BM;

    for (int i = tid; i < CIN * COUT / 4; i += 256) {
        int k = (i * 4) >> 7, c = (i * 4) & 127;
        const float* srcW = (c < 64) ? (Wmu + k * 64 + c) : (Wlv + k * 64 + c - 64);
        ((float4*)Ws)[i] = *(const float4*)srcW;
    }
    {
        constexpr int K4 = CIN / 4;
        for (int i = tid; i < BM * K4; i += 256) {
            int r = i / K4, k4 = i % K4;
            float4 v = make_float4(0.f, 0.f, 0.f, 0.f);
            int rg = row0 + r;
            if (rg < n) v = ((const float4*)(x + (size_t)rg * CIN))[k4];
            float* d = &As[r * CINP + k4 * 4];
            d[0] = v.x; d[1] = v.y; d[2] = v.z; d[3] = v.w;
        }
    }
    __syncthreads();

    u64 acc[TM][TN / 2];
    #pragma unroll
    for (int i = 0; i < TM; i++)
        #pragma unroll
        for (int j = 0; j < TN / 2; j++) acc[i][j] = 0ull;

    const float* Bp = Ws + tx * TN;
    #pragma unroll 8
    for (int k = 0; k < CIN; k++) {
        u64 a2[TM];
        #pragma unroll
        for (int i = 0; i < TM; i++) a2[i] = pack2(As[(ty + 16 * i) * CINP + k]);
        #pragma unroll
        for (int j4 = 0; j4 < TN / 4; j4++) {
            ulonglong2 bb = *(const ulonglong2*)(Bp + k * COUT + j4 * 4);
            #pragma unroll
            for (int i = 0; i < TM; i++) {
                ffma2(acc[i][j4 * 2 + 0], a2[i], bb.x);
                ffma2(acc[i][j4 * 2 + 1], a2[i], bb.y);
            }
        }
    }

    // stage mu|lv (+bias) into smem (reuses Ws/As region)
    __syncthreads();
    #pragma unroll
    for (int i = 0; i < TM; i++) {
        int rl = ty + 16 * i;
        #pragma unroll
        for (int j = 0; j < TN / 2; j++) {
            float c0, c1;
            unpack2(acc[i][j], c0, c1);
            int col = tx * TN + j * 2;
            if (col < 64) { c0 += bmu[col]; c1 += bmu[col + 1]; }
            else          { c0 += blv[col - 64]; c1 += blv[col - 63]; }
            *(float2*)(sm + rl * ZS + col) = make_float2(c0, c1);
        }
    }
    __syncthreads();

    // each thread: one half-row (32 z columns)
    {
        int rl = tid >> 1;
        int c0 = (tid & 1) * 32;
        int rg = row0 + rl;
        if (rg < n) {
            const float* mrow = sm + rl * ZS;
            #pragma unroll 8
            for (int c = c0; c < c0 + 32; c += 2) {
                float2 mu = *(const float2*)(mrow + c);
                float2 lv = *(const float2*)(mrow + 64 + c);
                float2 ep = *(const float2*)(eps + (size_t)rg * 64 + c);
                *(float2*)(out_mu + (size_t)rg * 64 + c) = mu;
                *(float2*)(out_lv + (size_t)rg * 64 + c) = lv;
                float2 zz;
                zz.x = mu.x + ep.x * expf(0.5f * lv.x);
                zz.y = mu.y + ep.y * expf(0.5f * lv.y);
                *(float2*)(z + (size_t)rg * 64 + c) = zz;
            }
        }
    }
}

// ---------------- CSR aggregation: warp per dst row, no atomics ----------
__global__ __launch_bounds__(256) void k_agg_csr128(
    const float* __restrict__ h, const float* __restrict__ bias,
    float* __restrict__ out, int n) {
    int warp = (blockIdx.x * blockDim.x + threadIdx.x) >> 5;
    int lane = threadIdx.x & 31;
    if (warp >= n) return;
    const float4* h4 = (const float4*)h;
    float4 b = ((const float4*)bias)[lane];
    float di = g_dinv[warp];
    float d2 = di * di;
    float4 hv = h4[(size_t)warp * 32 + lane];
    float4 acc0 = make_float4(b.x + d2 * hv.x, b.y + d2 * hv.y,
                              b.z + d2 * hv.z, b.w + d2 * hv.w);
    float4 acc1 = make_float4(0.f, 0.f, 0.f, 0.f);

    int beg = g_rowptr[warp], end = g_rowptr[warp + 1];
    for (int j0 = beg; j0 < end; j0 += 32) {
        int jj = j0 + lane;
        int2 cw = (jj < end) ? g_cw[jj] : make_int2(0, 0);
        int cnt = min(32, end - j0);
        #pragma unroll 4
        for (int t = 0; t < cnt; t++) {
            int ss = __shfl_sync(0xffffffffu, cw.x, t);
            float ww = __int_as_float(__shfl_sync(0xffffffffu, cw.y, t));
            float4 x4 = h4[(size_t)ss * 32 + lane];
            if (t & 1) {
                acc1.x = fmaf(ww, x4.x, acc1.x); acc1.y = fmaf(ww, x4.y, acc1.y);
                acc1.z = fmaf(ww, x4.z, acc1.z); acc1.w = fmaf(ww, x4.w, acc1.w);
            } else {
                acc0.x = fmaf(ww, x4.x, acc0.x); acc0.y = fmaf(ww, x4.y, acc0.y);
                acc0.z = fmaf(ww, x4.z, acc0.z); acc0.w = fmaf(ww, x4.w, acc0.w);
            }
        }
    }
    acc0.x += acc1.x; acc0.y += acc1.y; acc0.z += acc1.z; acc0.w += acc1.w;
    ((float4*)out)[(size_t)warp * 32 + lane] = acc0;
}

__global__ __launch_bounds__(256) void k_agg_csr64(
    const float* __restrict__ h, const float* __restrict__ bias,
    float* __restrict__ out, int n) {
    int warp = (blockIdx.x * blockDim.x + threadIdx.x) >> 5;
    int lane = threadIdx.x & 31;
    if (warp >= n) return;
    const float2* h2 = (const float2*)h;
    float2 b = bias ? ((const float2*)bias)[lane] : make_float2(0.f, 0.f);
    float di = g_dinv[warp];
    float d2 = di * di;
    float2 hv = h2[(size_t)warp * 32 + lane];
    float2 acc0 = make_float2(b.x + d2 * hv.x, b.y + d2 * hv.y);
    float2 acc1 = make_float2(0.f, 0.f);

    int beg = g_rowptr[warp], end = g_rowptr[warp + 1];
    for (int j0 = beg; j0 < end; j0 += 32) {
        int jj = j0 + lane;
        int2 cw = (jj < end) ? g_cw[jj] : make_int2(0, 0);
        int cnt = min(32, end - j0);
        #pragma unroll 4
        for (int t = 0; t < cnt; t++) {
            int ss = __shfl_sync(0xffffffffu, cw.x, t);
            float ww = __int_as_float(__shfl_sync(0xffffffffu, cw.y, t));
            float2 x2 = h2[(size_t)ss * 32 + lane];
            if (t & 1) {
                acc1.x = fmaf(ww, x2.x, acc1.x); acc1.y = fmaf(ww, x2.y, acc1.y);
            } else {
                acc0.x = fmaf(ww, x2.x, acc0.x); acc0.y = fmaf(ww, x2.y, acc0.y);
            }
        }
    }
    acc0.x += acc1.x; acc0.y += acc1.y;
    ((float2*)out)[(size_t)warp * 32 + lane] = acc0;
}

// ---------------- launch ----------------
extern "C" void kernel_launch(void* const* d_in, const int* in_sizes, int n_in,
                              void* d_out, int out_size) {
    const float* x    = (const float*)d_in[0];
    const int*   ei   = (const int*)d_in[1];
    const float* eps  = (const float*)d_in[2];
    const float* W_e1 = (const float*)d_in[3];
    const float* b_e1 = (const float*)d_in[4];
    const float* W_e2 = (const float*)d_in[5];
    const float* b_e2 = (const float*)d_in[6];
    const float* W_mu = (const float*)d_in[7];
    const float* b_mu = (const float*)d_in[8];
    const float* W_lv = (const float*)d_in[9];
    const float* b_lv = (const float*)d_in[10];
    const float* W_d1 = (const float*)d_in[11];
    const float* b_d1 = (const float*)d_in[12];
    const float* W_d2 = (const float*)d_in[13];
    const float* b_d2 = (const float*)d_in[14];

    const int n = in_sizes[0] / IC;  // 50000
    const int e = in_sizes[1] / 2;   // 800000
    const int* src = ei;
    const int* dst = ei + e;

    float *h, *a, *z;
    cudaGetSymbolAddress((void**)&h, g_h);
    cudaGetSymbolAddress((void**)&a, g_a);
    cudaGetSymbolAddress((void**)&z, g_z);

    float* out_d  = (float*)d_out;
    float* out_mu = out_d + (size_t)n * IC;
    float* out_lv = out_mu + (size_t)n * OC;

    const int T = 256;
    auto cdiv = [](long long v, int b) { return (int)((v + b - 1) / b); };

    const int SM_128_128 = (128 * 128 + 128 * 132) * 4;  // 133,120 B
    const int SM_128_64  = (128 * 64 + 128 * 132) * 4;   // 100,352 B
    const int SM_64_128  = (64 * 128 + 128 * 68) * 4;    //  67,584 B
    cudaFuncSetAttribute(k_gemm<128, 128, false, false>, cudaFuncAttributeMaxDynamicSharedMemorySize, SM_128_128);
    cudaFuncSetAttribute(k_gemm<128, 128, true, false>,  cudaFuncAttributeMaxDynamicSharedMemorySize, SM_128_128);
    cudaFuncSetAttribute(k_gemm<128, 64, true, false>,   cudaFuncAttributeMaxDynamicSharedMemorySize, SM_128_64);
    cudaFuncSetAttribute(k_gemm<64, 128, false, true>,   cudaFuncAttributeMaxDynamicSharedMemorySize, SM_64_128);
    cudaFuncSetAttribute(k_gemm_mulv_z,                  cudaFuncAttributeMaxDynamicSharedMemorySize, SM_64_128);

    const int GG = cdiv(n, 128);
    const int GA = cdiv((long long)n * 32, T);

    // CSR build
    k_zero_deg<<<cdiv(n, T), T>>>(n);
    k_deg_count<<<cdiv(cdiv(e, 4), T), T>>>(dst, e);
    k_scan<<<1, 1024>>>(n, e);
    k_scatter<<<cdiv(cdiv(e, 4), T), T>>>(src, dst, e);

    // encoder conv1: x[128] -> 128
    k_gemm<128, 128, false, false><<<GG, T, SM_128_128>>>(x, W_e1, nullptr, h, n);
    k_agg_csr128<<<GA, T>>>(h, b_e1, a, n);

    // encoder conv2: relu(a)[128] -> 64
    k_gemm<128, 64, true, false><<<GG, T, SM_128_64>>>(a, W_e2, nullptr, h, n);
    k_agg_csr64<<<GA, T>>>(h, b_e2, a, n);

    // mu|lv fused GEMM + reparameterize (writes out_mu, out_lv, z)
    k_gemm_mulv_z<<<GG, T, SM_64_128>>>(a, W_mu, W_lv, b_mu, b_lv, eps,
                                        out_mu, out_lv, z, n);

    // decoder conv1: (A z) W_d1 + b_d1  -- aggregate 64-wide FIRST (linearity)
    k_agg_csr64<<<GA, T>>>(z, nullptr, h, n);
    k_gemm<64, 128, false, true><<<GG, T, SM_64_128>>>(h, W_d1, b_d1, a, n);

    // decoder conv2: relu(a)[128] -> 128, aggregate into d_out
    k_gemm<128, 128, true, false><<<GG, T, SM_128_128>>>(a, W_d2, nullptr, h, n);
    k_agg_csr128<<<GA, T>>>(h, b_d2, out_d, n);
}